// round 16
// baseline (speedup 1.0000x reference)
#include <cuda_runtime.h>
#include <cstdint>
#include <math.h>

// ======================= device scratch =======================
#define PPAD 1280   // padded flat pixel dimension (34*34=1156 used)
// Y (conv1x1 out), TRANSPOSED, bf16 (hi,lo) interleaved: [z16][pp PPAD][ci/2=128] uint2
// zero-initialized at module load; borders never written -> stay zero across replays
__device__ __align__(16) uint2 g_Ysp[16 * PPAD * 128];
// w2 packed bf16 fragment-major: [tap9][cc8][m0t4][mblk8][sub2][lane32][word4]
__device__ __align__(16) uint32_t g_W2bh[9 * 8 * 4 * 2048];
__device__ __align__(16) uint32_t g_W2bl[9 * 8 * 4 * 2048];
__device__ __align__(16) float g_F[2 * 8 * 512 * 1024];
__device__ __align__(16) float g_S[8 * 512 * 512];
// BN partials: [t*512+co][144]  (b(8) x ntile(9) x ncol(2))
__device__ float g_psum[1024 * 144];
__device__ float g_psumq[1024 * 144];
__device__ float g_bn_a[1024];
__device__ float g_bn_c[1024];

#define LRELU 0.01f
#define BN_EPS 1e-5f
#define BSTW 40   // conv3x3 B smem row stride in words (32 data + 8 pad; 40%32=8 conflict-free)

__device__ __forceinline__ uint32_t fu(float x) { return __float_as_uint(x); }
__device__ __forceinline__ uint32_t smem_u32(const void* p) {
    uint32_t a;
    asm("{ .reg .u64 t; cvta.to.shared.u64 t, %1; cvt.u32.u64 %0, t; }" : "=r"(a) : "l"(p));
    return a;
}
// pack: high 16 bits = bf16(hi_val), low = bf16(lo_val)
__device__ __forceinline__ uint32_t packbf(float hi_val, float lo_val) {
    uint32_t r;
    asm("cvt.rn.bf16x2.f32 %0, %1, %2;" : "=r"(r) : "f"(hi_val), "f"(lo_val));
    return r;
}
__device__ __forceinline__ float lowf(uint32_t w)  { return __uint_as_float(w << 16); }
__device__ __forceinline__ float highf(uint32_t w) { return __uint_as_float(w & 0xffff0000u); }
// split pair (v0 lo-k, v1 hi-k) into hi word + residual word
__device__ __forceinline__ void splitbf(float v0, float v1, uint32_t& h, uint32_t& l) {
    h = packbf(v1, v0);
    l = packbf(v1 - highf(h), v0 - lowf(h));
}

#define MMA_BF16(d, a0, a1, a2, a3, b0v, b1v) \
    asm volatile("mma.sync.aligned.m16n8k16.row.col.f32.bf16.bf16.f32 " \
        "{%0,%1,%2,%3}, {%4,%5,%6,%7}, {%8,%9}, {%0,%1,%2,%3};" \
        : "+f"((d)[0]), "+f"((d)[1]), "+f"((d)[2]), "+f"((d)[3]) \
        : "r"(a0), "r"(a1), "r"(a2), "r"(a3), "r"(b0v), "r"(b1v))

#define CP16(saddr, gptr) \
    asm volatile("cp.async.ca.shared.global [%0], [%1], 16;" \
                 :: "r"((uint32_t)(saddr)), "l"(gptr) : "memory")
#define CP_COMMIT() asm volatile("cp.async.commit_group;" ::: "memory")
#define CP_WAIT_ALL() asm volatile("cp.async.wait_group 0;" ::: "memory")

// ======================= setup kernels =======================
// pack w2 -> bf16 hi/lo fragment-major words
// idx bits: word[0:2) lane[2:7) sub[7] mblk[8:11) m0t[11:13) cc[13:16) tap[16:)
__global__ void w2pack_kernel(const float* __restrict__ w2) {
    int idx = blockIdx.x * 256 + threadIdx.x;
    if (idx >= 9 * 8 * 4 * 2048) return;
    int w    = idx & 3;
    int lane = (idx >> 2) & 31;
    int sub  = (idx >> 7) & 1;
    int mblk = (idx >> 8) & 7;
    int m0t  = (idx >> 11) & 3;
    int cc   = (idx >> 13) & 7;
    int tap  = idx >> 16;
    int gg = lane >> 2, tq = lane & 3;
    int co  = m0t * 128 + mblk * 16 + gg + (w & 1) * 8;
    int cib = cc * 32 + sub * 16 + 2 * tq + (w >> 1) * 8;
    float v0 = w2[(size_t)co * 2304 + (size_t)cib * 9 + tap];
    float v1 = w2[(size_t)co * 2304 + (size_t)(cib + 1) * 9 + tap];
    uint32_t h, l;
    splitbf(v0, v1, h, l);
    g_W2bh[idx] = h;
    g_W2bl[idx] = l;
}

// ======================= conv 1x1 TRANSPOSED (bf16 3-term) -> Ysp ======
// Yt[p][ci] = sum_k X[k][p] * W1[ci][k].  M=1024 p, N=256 ci, K=512.
#define SMEM_C1 ((2 * 32 * 136 + 2 * 128 * 36) * 4)
__global__ __launch_bounds__(256, 2) void conv1x1t_kernel(
    const float* __restrict__ x1, const float* __restrict__ x2,
    const float* __restrict__ w1, const float* __restrict__ b1)
{
    extern __shared__ __align__(16) float smem[];
    float* sA = smem;                   // 2 x 4352
    float* sB = smem + 2 * 4352;        // 2 x 4608
    uint32_t sA32 = smem_u32(sA), sB32 = smem_u32(sB);

    int tid = threadIdx.x, wid = tid >> 5, lane = tid & 31;
    int g = lane >> 2, tq = lane & 3;
    int n0c = blockIdx.x * 128;   // ci tile
    int m0p = blockIdx.y * 128;   // pixel tile
    int z = blockIdx.z;
    const float* X = ((z >> 3) ? x2 : x1) + (size_t)(z & 7) * 512 * 1024;

    int wm = (wid & 3) * 32, wn = (wid >> 2) * 64;

    float acc[2][8][4];
    #pragma unroll
    for (int i = 0; i < 2; i++)
        #pragma unroll
        for (int j = 0; j < 8; j++)
            #pragma unroll
            for (int r = 0; r < 4; r++) acc[i][j][r] = 0.f;

    auto stageA = [&](int kc) {
        uint32_t base = sA32 + (uint32_t)((kc & 1) * 4352) * 4;
        #pragma unroll
        for (int v = 0; v < 4; v++) {
            int task = tid + v * 256;
            int k = task >> 5, c4 = task & 31;
            CP16(base + (k * 136 + c4 * 4) * 4, X + (size_t)(kc * 32 + k) * 1024 + m0p + c4 * 4);
        }
    };
    auto stageB = [&](int kc) {
        uint32_t base = sB32 + (uint32_t)((kc & 1) * 4608) * 4;
        #pragma unroll
        for (int v = 0; v < 4; v++) {
            int task = tid + v * 256;
            int c = task >> 3, k4 = task & 7;
            CP16(base + (c * 36 + k4 * 4) * 4, w1 + (size_t)(n0c + c) * 512 + kc * 32 + k4 * 4);
        }
    };

    stageA(0); stageB(0); CP_COMMIT();

    for (int kc = 0; kc < 16; kc++) {
        CP_WAIT_ALL();
        __syncthreads();
        if (kc < 15) { stageA(kc + 1); stageB(kc + 1); }
        CP_COMMIT();
        const float* sAp = sA + (kc & 1) * 4352;
        const float* sBp = sB + (kc & 1) * 4608;
        #pragma unroll
        for (int sub = 0; sub < 2; sub++) {
            uint32_t ah[2][4], al[2][4];
            #pragma unroll
            for (int i = 0; i < 2; i++) {
                const float* ap = sAp + (sub * 16 + 2 * tq) * 136 + wm + i * 16 + g;
                splitbf(ap[0],           ap[136],           ah[i][0], al[i][0]);
                splitbf(ap[8],           ap[136 + 8],       ah[i][1], al[i][1]);
                splitbf(ap[8 * 136],     ap[9 * 136],       ah[i][2], al[i][2]);
                splitbf(ap[8 * 136 + 8], ap[9 * 136 + 8],   ah[i][3], al[i][3]);
            }
            #pragma unroll
            for (int j = 0; j < 8; j++) {
                const float* bp = sBp + (wn + j * 8 + g) * 36 + sub * 16 + 2 * tq;
                uint32_t bh0, bl0, bh1, bl1;
                splitbf(bp[0], bp[1], bh0, bl0);
                splitbf(bp[8], bp[9], bh1, bl1);
                #pragma unroll
                for (int i = 0; i < 2; i++) {
                    MMA_BF16(acc[i][j], ah[i][0], ah[i][1], ah[i][2], ah[i][3], bh0, bh1);
                    MMA_BF16(acc[i][j], al[i][0], al[i][1], al[i][2], al[i][3], bh0, bh1);
                    MMA_BF16(acc[i][j], ah[i][0], ah[i][1], ah[i][2], ah[i][3], bl0, bl1);
                }
            }
        }
    }

    // epilogue: bias, bf16 hi/lo pack along ci pairs, store transposed interleaved
    #pragma unroll
    for (int j = 0; j < 8; j++) {
        int ci0 = n0c + wn + j * 8 + 2 * tq;
        float bj0 = b1[ci0], bj1 = b1[ci0 + 1];
        int widx0 = (n0c + wn) / 2 + j * 4 + tq;
        #pragma unroll
        for (int i = 0; i < 2; i++) {
            #pragma unroll
            for (int rh = 0; rh < 2; rh++) {
                float v0 = acc[i][j][rh * 2 + 0] + bj0;
                float v1 = acc[i][j][rh * 2 + 1] + bj1;
                uint32_t Wh, Wl;
                splitbf(v0, v1, Wh, Wl);
                int p = m0p + wm + i * 16 + g + rh * 8;
                int pp = 99 + (p >> 5) * 34 + (p & 31);
                g_Ysp[((size_t)z * PPAD + pp) * 128 + widx0] = make_uint2(Wh, Wl);
            }
        }
    }
}

// ======================= conv 3x3 via mma.sync bf16 3-term split ==========
// CTA 128co x 128n'. 8 warps 4m x 2n, warp tile 32m x 64n. mma m16n8k16.
// B: interleaved (hi,lo) uint2 rows [pixel 200][BSTW=40 words], LDS.64 fragments.
#define A_BUF_W 4096
#define B_ARR_W (200 * BSTW)
#define SMEM_CONV ((2 * A_BUF_W + B_ARR_W) * 4)

__global__ __launch_bounds__(256, 2) void conv3x3_bf16_kernel(const float* __restrict__ b2)
{
    extern __shared__ __align__(16) uint32_t smw[];
    uint32_t* sA = smw;                        // 2 x 4096
    uint32_t* sB = smw + 2 * A_BUF_W;          // 8000 words
    uint32_t sA32 = smem_u32(sA), sB32 = smem_u32(sB);

    int tid = threadIdx.x, wid = tid >> 5, lane = tid & 31;
    int g = lane >> 2, tq = lane & 3;
    int ntile = blockIdx.x;          // 0..8
    int m0y = blockIdx.y;
    int m0 = m0y * 128;
    int z = blockIdx.z;
    int nbase = ntile * 128;
    int s0 = 29 + nbase;

    int wm = (wid & 3) * 32;
    int wn = (wid >> 2) * 64;

    float acc[2][8][4];
    #pragma unroll
    for (int i = 0; i < 2; i++)
        #pragma unroll
        for (int j = 0; j < 8; j++)
            #pragma unroll
            for (int r = 0; r < 4; r++) acc[i][j][r] = 0.f;

    auto stageA = [&](int it) {
        int tap = it % 9, cc = it / 9;
        size_t blk = (((size_t)tap * 8 + cc) * 4 + m0y) * 2048;
        uint32_t base = sA32 + (uint32_t)((it & 1) * A_BUF_W) * 4;
        #pragma unroll
        for (int v = 0; v < 4; v++) {
            int task = tid + v * 256;
            int arr = task >= 512;
            int e = task & 511;
            const uint32_t* src = (arr ? g_W2bl : g_W2bh) + blk + e * 4;
            CP16(base + (arr * 2048 + e * 4) * 4, src);
        }
    };
    // 200 rows x 8 CP16 (each 2 uint2 = 4 words) = 1600 tasks
    auto stageB = [&](int cc) {
        size_t rowbase = (size_t)z * PPAD + s0;
        #pragma unroll
        for (int v = 0; v < 7; v++) {
            int i = tid + v * 256;
            if (i < 1600) {
                int row = i >> 3;
                int c2 = i & 7;
                const uint2* src = g_Ysp + (rowbase + row) * 128 + cc * 16 + c2 * 2;
                CP16(sB32 + (row * BSTW + c2 * 4) * 4, src);
            }
        }
    };

    stageA(0);
    stageB(0);
    CP_COMMIT();

    for (int it = 0; it < 72; ++it) {
        int tap = it % 9, cc = it / 9;
        int dh = tap / 3, dw = tap - dh * 3;

        CP_WAIT_ALL();
        __syncthreads();

        if (it < 71) stageA(it + 1);
        CP_COMMIT();

        const uint32_t* sAp = sA + (it & 1) * A_BUF_W;
        int rowoff = dh * 34 + dw + wn + g;

        #pragma unroll
        for (int sub = 0; sub < 2; sub++) {
            uint32_t ah[2][4], al[2][4];
            #pragma unroll
            for (int i = 0; i < 2; i++) {
                int mblk = (wm >> 4) + i;
                uint4 vh = *(const uint4*)&sAp[((mblk * 2 + sub) * 32 + lane) * 4];
                uint4 vl = *(const uint4*)&sAp[2048 + ((mblk * 2 + sub) * 32 + lane) * 4];
                ah[i][0] = vh.x; ah[i][1] = vh.y; ah[i][2] = vh.z; ah[i][3] = vh.w;
                al[i][0] = vl.x; al[i][1] = vl.y; al[i][2] = vl.z; al[i][3] = vl.w;
            }
            #pragma unroll
            for (int j = 0; j < 8; j++) {
                int wbase = (rowoff + j * 8) * BSTW + (sub * 8 + tq) * 2;
                uint2 p0 = *(const uint2*)&sB[wbase];
                uint2 p1 = *(const uint2*)&sB[wbase + 8];
                #pragma unroll
                for (int i = 0; i < 2; i++) {
                    MMA_BF16(acc[i][j], ah[i][0], ah[i][1], ah[i][2], ah[i][3], p0.x, p1.x);
                    MMA_BF16(acc[i][j], al[i][0], al[i][1], al[i][2], al[i][3], p0.x, p1.x);
                    MMA_BF16(acc[i][j], ah[i][0], ah[i][1], ah[i][2], ah[i][3], p0.y, p1.y);
                }
            }
        }

        if (tap == 8 && cc < 7) {
            __syncthreads();
            stageB(cc + 1);
            CP_COMMIT();
        }
    }

    // ---- epilogue: bias + LeakyReLU + store F + BN partials ----
    int timg = z >> 3, b = z & 7;
    int ncol = wid >> 2;
    float bias[2][2], psv[2][2] = {}, pqv[2][2] = {};
    #pragma unroll
    for (int i = 0; i < 2; i++)
        #pragma unroll
        for (int rh = 0; rh < 2; rh++)
            bias[i][rh] = b2[m0 + wm + i * 16 + g + rh * 8];

    #pragma unroll
    for (int i = 0; i < 2; i++) {
        #pragma unroll
        for (int j = 0; j < 8; j++) {
            #pragma unroll
            for (int r = 0; r < 4; r++) {
                int rh = r >> 1, c = r & 1;
                int m = wm + i * 16 + g + rh * 8;
                int np = nbase + wn + j * 8 + 2 * tq + c;
                int row = np / 34;
                int col = np - row * 34;
                if (row >= 1 && row <= 32 && col >= 1 && col <= 32) {
                    float v = acc[i][j][r] + bias[i][rh];
                    v = v > 0.f ? v : LRELU * v;
                    g_F[((size_t)z * 512 + m0 + m) * 1024 + (row - 1) * 32 + (col - 1)] = v;
                    psv[i][rh] += v;
                    pqv[i][rh] += v * v;
                }
            }
        }
    }
    #pragma unroll
    for (int i = 0; i < 2; i++) {
        #pragma unroll
        for (int rh = 0; rh < 2; rh++) {
            float s = psv[i][rh], q = pqv[i][rh];
            s += __shfl_xor_sync(0xffffffffu, s, 1);
            s += __shfl_xor_sync(0xffffffffu, s, 2);
            q += __shfl_xor_sync(0xffffffffu, q, 1);
            q += __shfl_xor_sync(0xffffffffu, q, 2);
            if (tq == 0) {
                int ch = timg * 512 + m0 + wm + i * 16 + g + rh * 8;
                int slot = (b * 9 + ntile) * 2 + ncol;
                g_psum [(size_t)ch * 144 + slot] = s;
                g_psumq[(size_t)ch * 144 + slot] = q;
            }
        }
    }
}

// ======================= BN stats =======================
__global__ void bn_stats_kernel(const float* __restrict__ gamma,
                                const float* __restrict__ bn_bias)
{
    int i = blockIdx.x * blockDim.x + threadIdx.x;
    if (i >= 1024) return;
    float s = 0.f, q = 0.f;
    #pragma unroll 8
    for (int p = 0; p < 144; p++) {
        s += g_psum [(size_t)i * 144 + p];
        q += g_psumq[(size_t)i * 144 + p];
    }
    const float inv_n = 1.0f / 8192.0f;
    float mean = s * inv_n;
    float var = q * inv_n - mean * mean;
    float a = gamma[i & 511] * rsqrtf(var + BN_EPS);
    g_bn_a[i] = a;
    g_bn_c[i] = bn_bias[i & 511] - mean * a;
}

// ======================= scores GEMM (BN folded, bf16 3-term) =======
#define SMEM_SC ((4 * 128 * 36) * 4)
__global__ __launch_bounds__(256, 2) void scores_mma_kernel()
{
    extern __shared__ __align__(16) float smem[];
    float* sA = smem;
    float* sB = smem + 2 * 4608;
    uint32_t sA32 = smem_u32(sA), sB32 = smem_u32(sB);

    int tid = threadIdx.x, wid = tid >> 5, lane = tid & 31;
    int g = lane >> 2, tq = lane & 3;
    int n0 = blockIdx.x * 128, m0 = blockIdx.y * 128, b = blockIdx.z;
    const float* Ag = g_F + (size_t)b * 512 * 1024;
    const float* Bg = g_F + (size_t)(8 + b) * 512 * 1024;

    int wm = (wid & 3) * 32, wn = (wid >> 2) * 64;

    float asc[2][2], aof[2][2], bsc[8], bof[8];
    #pragma unroll
    for (int i = 0; i < 2; i++)
        #pragma unroll
        for (int rh = 0; rh < 2; rh++) {
            int ch = m0 + wm + i * 16 + g + rh * 8;
            asc[i][rh] = g_bn_a[ch];
            aof[i][rh] = g_bn_c[ch];
        }
    #pragma unroll
    for (int j = 0; j < 8; j++) {
        int ch = 512 + n0 + wn + j * 8 + g;
        bsc[j] = g_bn_a[ch];
        bof[j] = g_bn_c[ch];
    }

    float acc[2][8][4];
    #pragma unroll
    for (int i = 0; i < 2; i++)
        #pragma unroll
        for (int j = 0; j < 8; j++)
            #pragma unroll
            for (int r = 0; r < 4; r++) acc[i][j][r] = 0.f;

    auto stage = [&](int kc) {
        uint32_t baseA = sA32 + (uint32_t)((kc & 1) * 4608) * 4;
        uint32_t baseB = sB32 + (uint32_t)((kc & 1) * 4608) * 4;
        #pragma unroll
        for (int v = 0; v < 4; v++) {
            int task = tid + v * 256;
            int m = task >> 3, c4 = task & 7;
            CP16(baseA + (m * 36 + c4 * 4) * 4, Ag + (size_t)(m0 + m) * 1024 + kc * 32 + c4 * 4);
            CP16(baseB + (m * 36 + c4 * 4) * 4, Bg + (size_t)(n0 + m) * 1024 + kc * 32 + c4 * 4);
        }
    };

    stage(0); CP_COMMIT();

    for (int kc = 0; kc < 32; kc++) {
        CP_WAIT_ALL();
        __syncthreads();
        if (kc < 31) stage(kc + 1);
        CP_COMMIT();
        const float* sAp = sA + (kc & 1) * 4608;
        const float* sBp = sB + (kc & 1) * 4608;
        #pragma unroll
        for (int sub = 0; sub < 2; sub++) {
            uint32_t ah[2][4], al[2][4];
            #pragma unroll
            for (int i = 0; i < 2; i++) {
                const float* ap  = sAp + (wm + i * 16 + g) * 36 + sub * 16 + 2 * tq;
                const float* ap8 = ap + 8 * 36;
                float v00 = fmaf(ap[0],  asc[i][0], aof[i][0]);
                float v01 = fmaf(ap[1],  asc[i][0], aof[i][0]);
                float v02 = fmaf(ap[8],  asc[i][0], aof[i][0]);
                float v03 = fmaf(ap[9],  asc[i][0], aof[i][0]);
                float v10 = fmaf(ap8[0], asc[i][1], aof[i][1]);
                float v11 = fmaf(ap8[1], asc[i][1], aof[i][1]);
                float v12 = fmaf(ap8[8], asc[i][1], aof[i][1]);
                float v13 = fmaf(ap8[9], asc[i][1], aof[i][1]);
                splitbf(v00, v01, ah[i][0], al[i][0]);
                splitbf(v10, v11, ah[i][1], al[i][1]);
                splitbf(v02, v03, ah[i][2], al[i][2]);
                splitbf(v12, v13, ah[i][3], al[i][3]);
            }
            #pragma unroll
            for (int j = 0; j < 8; j++) {
                const float* bp = sBp + (wn + j * 8 + g) * 36 + sub * 16 + 2 * tq;
                float b0 = fmaf(bp[0], bsc[j], bof[j]);
                float b1 = fmaf(bp[1], bsc[j], bof[j]);
                float b2 = fmaf(bp[8], bsc[j], bof[j]);
                float b3 = fmaf(bp[9], bsc[j], bof[j]);
                uint32_t bh0, bl0, bh1, bl1;
                splitbf(b0, b1, bh0, bl0);
                splitbf(b2, b3, bh1, bl1);
                #pragma unroll
                for (int i = 0; i < 2; i++) {
                    MMA_BF16(acc[i][j], ah[i][0], ah[i][1], ah[i][2], ah[i][3], bh0, bh1);
                    MMA_BF16(acc[i][j], al[i][0], al[i][1], al[i][2], al[i][3], bh0, bh1);
                    MMA_BF16(acc[i][j], ah[i][0], ah[i][1], ah[i][2], ah[i][3], bl0, bl1);
                }
            }
        }
    }

    float* S = g_S + (size_t)b * 512 * 512;
    #pragma unroll
    for (int i = 0; i < 2; i++)
        #pragma unroll
        for (int j = 0; j < 8; j++)
            #pragma unroll
            for (int r = 0; r < 4; r++) {
                int m = m0 + wm + i * 16 + g + (r >> 1) * 8;
                int n = n0 + wn + j * 8 + 2 * tq + (r & 1);
                S[(size_t)m * 512 + n] = acc[i][j][r];
            }
}

// ======================= softmax =======================
__global__ void softmax_kernel()
{
    int row = blockIdx.x;
    float* s = g_S + (size_t)row * 512;
    int tid = threadIdx.x;

    float v0 = s[tid], v1 = s[tid + 256];
    float m = fmaxf(v0, v1);
    __shared__ float red[8];
    #pragma unroll
    for (int o = 16; o > 0; o >>= 1)
        m = fmaxf(m, __shfl_xor_sync(0xffffffffu, m, o));
    if ((tid & 31) == 0) red[tid >> 5] = m;
    __syncthreads();
    float M = fmaxf(fmaxf(fmaxf(red[0], red[1]), fmaxf(red[2], red[3])),
                    fmaxf(fmaxf(red[4], red[5]), fmaxf(red[6], red[7])));
    __syncthreads();

    float e0 = expf(v0 - M), e1 = expf(v1 - M);
    float sum = e0 + e1;
    #pragma unroll
    for (int o = 16; o > 0; o >>= 1)
        sum += __shfl_xor_sync(0xffffffffu, sum, o);
    if ((tid & 31) == 0) red[tid >> 5] = sum;
    __syncthreads();
    float T = red[0] + red[1] + red[2] + red[3] + red[4] + red[5] + red[6] + red[7];
    float inv = 1.0f / T;
    s[tid] = e0 * inv;
    s[tid + 256] = e1 * inv;
}

// ======================= out GEMM (bf16 3-term) ==========
#define SMEM_OUT ((2 * 128 * 36 + 2 * 32 * 140) * 4)
__global__ __launch_bounds__(256, 2) void out_mma_kernel(
    const float* __restrict__ x, const float* __restrict__ beta,
    float* __restrict__ out)
{
    extern __shared__ __align__(16) float smem[];
    float* sA = smem;
    float* sB = smem + 2 * 4608;
    uint32_t sA32 = smem_u32(sA), sB32 = smem_u32(sB);

    int tid = threadIdx.x, wid = tid >> 5, lane = tid & 31;
    int g = lane >> 2, tq = lane & 3;
    int n0 = blockIdx.x * 128, m0 = blockIdx.y * 128, b = blockIdx.z;
    const float* Ag = g_S + (size_t)b * 512 * 512;
    const float* X = x + (size_t)b * 512 * 1024;

    int wm = (wid & 3) * 32, wn = (wid >> 2) * 64;

    float acc[2][8][4];
    #pragma unroll
    for (int i = 0; i < 2; i++)
        #pragma unroll
        for (int j = 0; j < 8; j++)
            #pragma unroll
            for (int r = 0; r < 4; r++) acc[i][j][r] = 0.f;

    auto stageA = [&](int kc) {
        uint32_t base = sA32 + (uint32_t)((kc & 1) * 4608) * 4;
        #pragma unroll
        for (int v = 0; v < 4; v++) {
            int task = tid + v * 256;
            int m = task >> 3, c4 = task & 7;
            CP16(base + (m * 36 + c4 * 4) * 4, Ag + (size_t)(m0 + m) * 512 + kc * 32 + c4 * 4);
        }
    };
    auto stageB = [&](int kc) {
        uint32_t base = sB32 + (uint32_t)((kc & 1) * 4480) * 4;
        #pragma unroll
        for (int v = 0; v < 4; v++) {
            int task = tid + v * 256;
            int k = task >> 5, c4 = task & 31;
            CP16(base + (k * 140 + c4 * 4) * 4, X + (size_t)(kc * 32 + k) * 1024 + n0 + c4 * 4);
        }
    };

    stageA(0); stageB(0); CP_COMMIT();

    for (int kc = 0; kc < 16; kc++) {
        CP_WAIT_ALL();
        __syncthreads();
        if (kc < 15) { stageA(kc + 1); stageB(kc + 1); }
        CP_COMMIT();
        const float* sAp = sA + (kc & 1) * 4608;
        const float* sBp = sB + (kc & 1) * 4480;
        #pragma unroll
        for (int sub = 0; sub < 2; sub++) {
            uint32_t ah[2][4], al[2][4];
            #pragma unroll
            for (int i = 0; i < 2; i++) {
                const float* ap  = sAp + (wm + i * 16 + g) * 36 + sub * 16 + 2 * tq;
                const float* ap8 = ap + 8 * 36;
                splitbf(ap[0],  ap[1],  ah[i][0], al[i][0]);
                splitbf(ap8[0], ap8[1], ah[i][1], al[i][1]);
                splitbf(ap[8],  ap[9],  ah[i][2], al[i][2]);
                splitbf(ap8[8], ap8[9], ah[i][3], al[i][3]);
            }
            #pragma unroll
            for (int j = 0; j < 8; j++) {
                const float* bp = sBp + (sub * 16 + 2 * tq) * 140 + wn + j * 8 + g;
                uint32_t bh0, bl0, bh1, bl1;
                splitbf(bp[0],       bp[140],       bh0, bl0);
                splitbf(bp[8 * 140], bp[9 * 140],   bh1, bl1);
                #pragma unroll
                for (int i = 0; i < 2; i++) {
                    MMA_BF16(acc[i][j], ah[i][0], ah[i][1], ah[i][2], ah[i][3], bh0, bh1);
                    MMA_BF16(acc[i][j], al[i][0], al[i][1], al[i][2], al[i][3], bh0, bh1);
                    MMA_BF16(acc[i][j], ah[i][0], ah[i][1], ah[i][2], ah[i][3], bl0, bl1);
                }
            }
        }
    }

    float bt = beta[0];
    float* O = out + (size_t)b * 512 * 1024;
    #pragma unroll
    for (int i = 0; i < 2; i++)
        #pragma unroll
        for (int j = 0; j < 8; j++)
            #pragma unroll
            for (int r = 0; r < 4; r++) {
                int m = m0 + wm + i * 16 + g + (r >> 1) * 8;
                int n = n0 + wn + j * 8 + 2 * tq + (r & 1);
                O[(size_t)m * 1024 + n] = bt * acc[i][j][r];
            }
}

// ======================= launch =======================
extern "C" void kernel_launch(void* const* d_in, const int* in_sizes, int n_in,
                              void* d_out, int out_size)
{
    const float* x     = (const float*)d_in[0];
    const float* x1    = (const float*)d_in[1];
    const float* x2    = (const float*)d_in[2];
    const float* w1    = (const float*)d_in[3];
    const float* b1    = (const float*)d_in[4];
    const float* w2    = (const float*)d_in[5];
    const float* b2    = (const float*)d_in[6];
    const float* gamma = (const float*)d_in[7];
    const float* bnb   = (const float*)d_in[8];
    const float* beta  = (const float*)d_in[9];
    float* out = (float*)d_out;

    static int smem_set = 0;
    if (!smem_set) {
        cudaFuncSetAttribute(conv1x1t_kernel,     cudaFuncAttributeMaxDynamicSharedMemorySize, SMEM_C1);
        cudaFuncSetAttribute(conv3x3_bf16_kernel, cudaFuncAttributeMaxDynamicSharedMemorySize, SMEM_CONV);
        cudaFuncSetAttribute(scores_mma_kernel,   cudaFuncAttributeMaxDynamicSharedMemorySize, SMEM_SC);
        cudaFuncSetAttribute(out_mma_kernel,      cudaFuncAttributeMaxDynamicSharedMemorySize, SMEM_OUT);
        smem_set = 1;
    }

    w2pack_kernel<<<(9 * 8 * 4 * 2048 + 255) / 256, 256>>>(w2);

    conv1x1t_kernel<<<dim3(2, 8, 16), 256, SMEM_C1>>>(x1, x2, w1, b1);

    conv3x3_bf16_kernel<<<dim3(9, 4, 16), 256, SMEM_CONV>>>(b2);

    bn_stats_kernel<<<4, 256>>>(gamma, bnb);

    scores_mma_kernel<<<dim3(4, 4, 8), 256, SMEM_SC>>>();
    softmax_kernel<<<4096, 256>>>();

    out_mma_kernel<<<dim3(8, 4, 8), 256, SMEM_OUT>>>(x, beta, out);
}

// round 17
// speedup vs baseline: 1.1261x; 1.1261x over previous
#include <cuda_runtime.h>
#include <cstdint>
#include <math.h>

// ======================= device scratch =======================
#define PPAD 1280   // padded flat pixel dimension (34*34=1156 used)
// Y (conv1x1 out), TRANSPOSED + bf16-packed along ci: [z16][pp PPAD][ci/2=128] uint32
// zero-initialized at module load; borders never written -> stay zero across replays
__device__ __align__(16) uint32_t g_Ybh[16 * PPAD * 128];
__device__ __align__(16) uint32_t g_Ybl[16 * PPAD * 128];
// w2 packed bf16 fragment-major: [tap9][cc8][m0t4][mblk8][sub2][lane32][word4]
__device__ __align__(16) uint32_t g_W2bh[9 * 8 * 4 * 2048];
__device__ __align__(16) uint32_t g_W2bl[9 * 8 * 4 * 2048];
__device__ __align__(16) float g_F[2 * 8 * 512 * 1024];
__device__ __align__(16) float g_S[8 * 512 * 512];
// BN partials: [t*512+co][144]  (b(8) x ntile(9) x ncol(2))
__device__ float g_psum[1024 * 144];
__device__ float g_psumq[1024 * 144];
__device__ float g_bn_a[1024];
__device__ float g_bn_c[1024];

#define LRELU 0.01f
#define BN_EPS 1e-5f
#define BSTW 20   // conv3x3 B smem row stride in words (conflict-free)

__device__ __forceinline__ uint32_t fu(float x) { return __float_as_uint(x); }
__device__ __forceinline__ uint32_t smem_u32(const void* p) {
    uint32_t a;
    asm("{ .reg .u64 t; cvta.to.shared.u64 t, %1; cvt.u32.u64 %0, t; }" : "=r"(a) : "l"(p));
    return a;
}
// pack: high 16 bits = bf16(hi_val), low = bf16(lo_val)
__device__ __forceinline__ uint32_t packbf(float hi_val, float lo_val) {
    uint32_t r;
    asm("cvt.rn.bf16x2.f32 %0, %1, %2;" : "=r"(r) : "f"(hi_val), "f"(lo_val));
    return r;
}
__device__ __forceinline__ float lowf(uint32_t w)  { return __uint_as_float(w << 16); }
__device__ __forceinline__ float highf(uint32_t w) { return __uint_as_float(w & 0xffff0000u); }
// split pair (v0 lo-k, v1 hi-k) into hi word + residual word
__device__ __forceinline__ void splitbf(float v0, float v1, uint32_t& h, uint32_t& l) {
    h = packbf(v1, v0);
    l = packbf(v1 - highf(h), v0 - lowf(h));
}

#define MMA_BF16(d, a0, a1, a2, a3, b0v, b1v) \
    asm volatile("mma.sync.aligned.m16n8k16.row.col.f32.bf16.bf16.f32 " \
        "{%0,%1,%2,%3}, {%4,%5,%6,%7}, {%8,%9}, {%0,%1,%2,%3};" \
        : "+f"((d)[0]), "+f"((d)[1]), "+f"((d)[2]), "+f"((d)[3]) \
        : "r"(a0), "r"(a1), "r"(a2), "r"(a3), "r"(b0v), "r"(b1v))

#define CP16(saddr, gptr) \
    asm volatile("cp.async.ca.shared.global [%0], [%1], 16;" \
                 :: "r"((uint32_t)(saddr)), "l"(gptr) : "memory")
#define CP_COMMIT() asm volatile("cp.async.commit_group;" ::: "memory")
#define CP_WAIT_ALL() asm volatile("cp.async.wait_group 0;" ::: "memory")

// ======================= setup kernels =======================
// pack w2 -> bf16 hi/lo fragment-major words
// idx bits: word[0:2) lane[2:7) sub[7] mblk[8:11) m0t[11:13) cc[13:16) tap[16:)
__global__ void w2pack_kernel(const float* __restrict__ w2) {
    int idx = blockIdx.x * 256 + threadIdx.x;
    if (idx >= 9 * 8 * 4 * 2048) return;
    int w    = idx & 3;
    int lane = (idx >> 2) & 31;
    int sub  = (idx >> 7) & 1;
    int mblk = (idx >> 8) & 7;
    int m0t  = (idx >> 11) & 3;
    int cc   = (idx >> 13) & 7;
    int tap  = idx >> 16;
    int gg = lane >> 2, tq = lane & 3;
    int co  = m0t * 128 + mblk * 16 + gg + (w & 1) * 8;
    int cib = cc * 32 + sub * 16 + 2 * tq + (w >> 1) * 8;
    float v0 = w2[(size_t)co * 2304 + (size_t)cib * 9 + tap];
    float v1 = w2[(size_t)co * 2304 + (size_t)(cib + 1) * 9 + tap];
    uint32_t h, l;
    splitbf(v0, v1, h, l);
    g_W2bh[idx] = h;
    g_W2bl[idx] = l;
}

// ======================= conv 1x1 TRANSPOSED (bf16 3-term) -> Ybh/Ybl ======
// Yt[p][ci] = sum_k X[k][p] * W1[ci][k].  M=1024 p, N=256 ci, K=512.
#define SMEM_C1 ((2 * 32 * 136 + 2 * 128 * 36) * 4)
__global__ __launch_bounds__(256, 2) void conv1x1t_kernel(
    const float* __restrict__ x1, const float* __restrict__ x2,
    const float* __restrict__ w1, const float* __restrict__ b1)
{
    extern __shared__ __align__(16) float smem[];
    float* sA = smem;                   // 2 x 4352
    float* sB = smem + 2 * 4352;        // 2 x 4608
    uint32_t sA32 = smem_u32(sA), sB32 = smem_u32(sB);

    int tid = threadIdx.x, wid = tid >> 5, lane = tid & 31;
    int g = lane >> 2, tq = lane & 3;
    int n0c = blockIdx.x * 128;   // ci tile
    int m0p = blockIdx.y * 128;   // pixel tile
    int z = blockIdx.z;
    const float* X = ((z >> 3) ? x2 : x1) + (size_t)(z & 7) * 512 * 1024;

    int wm = (wid & 3) * 32, wn = (wid >> 2) * 64;

    float acc[2][8][4];
    #pragma unroll
    for (int i = 0; i < 2; i++)
        #pragma unroll
        for (int j = 0; j < 8; j++)
            #pragma unroll
            for (int r = 0; r < 4; r++) acc[i][j][r] = 0.f;

    auto stageA = [&](int kc) {
        uint32_t base = sA32 + (uint32_t)((kc & 1) * 4352) * 4;
        #pragma unroll
        for (int v = 0; v < 4; v++) {
            int task = tid + v * 256;
            int k = task >> 5, c4 = task & 31;
            CP16(base + (k * 136 + c4 * 4) * 4, X + (size_t)(kc * 32 + k) * 1024 + m0p + c4 * 4);
        }
    };
    auto stageB = [&](int kc) {
        uint32_t base = sB32 + (uint32_t)((kc & 1) * 4608) * 4;
        #pragma unroll
        for (int v = 0; v < 4; v++) {
            int task = tid + v * 256;
            int c = task >> 3, k4 = task & 7;
            CP16(base + (c * 36 + k4 * 4) * 4, w1 + (size_t)(n0c + c) * 512 + kc * 32 + k4 * 4);
        }
    };

    stageA(0); stageB(0); CP_COMMIT();

    for (int kc = 0; kc < 16; kc++) {
        CP_WAIT_ALL();
        __syncthreads();
        if (kc < 15) { stageA(kc + 1); stageB(kc + 1); }
        CP_COMMIT();
        const float* sAp = sA + (kc & 1) * 4352;
        const float* sBp = sB + (kc & 1) * 4608;
        #pragma unroll
        for (int sub = 0; sub < 2; sub++) {
            uint32_t ah[2][4], al[2][4];
            #pragma unroll
            for (int i = 0; i < 2; i++) {
                const float* ap = sAp + (sub * 16 + 2 * tq) * 136 + wm + i * 16 + g;
                splitbf(ap[0],           ap[136],           ah[i][0], al[i][0]);
                splitbf(ap[8],           ap[136 + 8],       ah[i][1], al[i][1]);
                splitbf(ap[8 * 136],     ap[9 * 136],       ah[i][2], al[i][2]);
                splitbf(ap[8 * 136 + 8], ap[9 * 136 + 8],   ah[i][3], al[i][3]);
            }
            #pragma unroll
            for (int j = 0; j < 8; j++) {
                const float* bp = sBp + (wn + j * 8 + g) * 36 + sub * 16 + 2 * tq;
                uint32_t bh0, bl0, bh1, bl1;
                splitbf(bp[0], bp[1], bh0, bl0);
                splitbf(bp[8], bp[9], bh1, bl1);
                #pragma unroll
                for (int i = 0; i < 2; i++) {
                    MMA_BF16(acc[i][j], ah[i][0], ah[i][1], ah[i][2], ah[i][3], bh0, bh1);
                    MMA_BF16(acc[i][j], al[i][0], al[i][1], al[i][2], al[i][3], bh0, bh1);
                    MMA_BF16(acc[i][j], ah[i][0], ah[i][1], ah[i][2], ah[i][3], bl0, bl1);
                }
            }
        }
    }

    // epilogue: bias, bf16 hi/lo pack along ci pairs, store transposed
    #pragma unroll
    for (int j = 0; j < 8; j++) {
        int ci0 = n0c + wn + j * 8 + 2 * tq;
        float bj0 = b1[ci0], bj1 = b1[ci0 + 1];
        int widx0 = (n0c + wn) / 2 + j * 4 + tq;
        #pragma unroll
        for (int i = 0; i < 2; i++) {
            #pragma unroll
            for (int rh = 0; rh < 2; rh++) {
                float v0 = acc[i][j][rh * 2 + 0] + bj0;
                float v1 = acc[i][j][rh * 2 + 1] + bj1;
                uint32_t Wh, Wl;
                splitbf(v0, v1, Wh, Wl);
                int p = m0p + wm + i * 16 + g + rh * 8;
                int pp = 99 + (p >> 5) * 34 + (p & 31);
                size_t idx = ((size_t)z * PPAD + pp) * 128 + widx0;
                g_Ybh[idx] = Wh;
                g_Ybl[idx] = Wl;
            }
        }
    }
}

// ======================= conv 3x3 via mma.sync bf16 3-term split ==========
// (R14/R15 winner layout: separate hi/lo arrays, BSTW=20)
#define A_BUF_W 4096
#define B_ARR_W (200 * BSTW)
#define SMEM_CONV ((2 * A_BUF_W + 2 * B_ARR_W) * 4)

__global__ __launch_bounds__(256, 2) void conv3x3_bf16_kernel(const float* __restrict__ b2)
{
    extern __shared__ __align__(16) uint32_t smw[];
    uint32_t* sA = smw;                        // 2 x 4096
    uint32_t* sB = smw + 2 * A_BUF_W;          // hi 4000, lo 4000
    uint32_t sA32 = smem_u32(sA), sB32 = smem_u32(sB);

    int tid = threadIdx.x, wid = tid >> 5, lane = tid & 31;
    int g = lane >> 2, tq = lane & 3;
    int ntile = blockIdx.x;          // 0..8
    int m0y = blockIdx.y;
    int m0 = m0y * 128;
    int z = blockIdx.z;
    int nbase = ntile * 128;
    int s0 = 29 + nbase;

    int wm = (wid & 3) * 32;
    int wn = (wid >> 2) * 64;

    float acc[2][8][4];
    #pragma unroll
    for (int i = 0; i < 2; i++)
        #pragma unroll
        for (int j = 0; j < 8; j++)
            #pragma unroll
            for (int r = 0; r < 4; r++) acc[i][j][r] = 0.f;

    auto stageA = [&](int it) {
        int tap = it % 9, cc = it / 9;
        size_t blk = (((size_t)tap * 8 + cc) * 4 + m0y) * 2048;
        uint32_t base = sA32 + (uint32_t)((it & 1) * A_BUF_W) * 4;
        #pragma unroll
        for (int v = 0; v < 4; v++) {
            int task = tid + v * 256;
            int arr = task >= 512;
            int e = task & 511;
            const uint32_t* src = (arr ? g_W2bl : g_W2bh) + blk + e * 4;
            CP16(base + (arr * 2048 + e * 4) * 4, src);
        }
    };
    auto stageB = [&](int cc) {
        size_t rowbase = (size_t)z * PPAD + s0;
        #pragma unroll
        for (int v = 0; v < 7; v++) {
            int i = tid + v * 256;
            if (i < 1600) {
                int arr = i >= 800;
                int rem = i - arr * 800;
                int row = rem >> 2;
                int c4 = rem & 3;
                const uint32_t* src = (arr ? g_Ybl : g_Ybh)
                                      + (rowbase + row) * 128 + cc * 16 + c4 * 4;
                CP16(sB32 + (arr * B_ARR_W + row * BSTW + c4 * 4) * 4, src);
            }
        }
    };

    stageA(0);
    stageB(0);
    CP_COMMIT();

    for (int it = 0; it < 72; ++it) {
        int tap = it % 9, cc = it / 9;
        int dh = tap / 3, dw = tap - dh * 3;

        CP_WAIT_ALL();
        __syncthreads();

        if (it < 71) stageA(it + 1);
        CP_COMMIT();

        const uint32_t* sAp = sA + (it & 1) * A_BUF_W;
        int rowoff = dh * 34 + dw + wn + g;

        #pragma unroll
        for (int sub = 0; sub < 2; sub++) {
            uint32_t ah[2][4], al[2][4];
            #pragma unroll
            for (int i = 0; i < 2; i++) {
                int mblk = (wm >> 4) + i;
                uint4 vh = *(const uint4*)&sAp[((mblk * 2 + sub) * 32 + lane) * 4];
                uint4 vl = *(const uint4*)&sAp[2048 + ((mblk * 2 + sub) * 32 + lane) * 4];
                ah[i][0] = vh.x; ah[i][1] = vh.y; ah[i][2] = vh.z; ah[i][3] = vh.w;
                al[i][0] = vl.x; al[i][1] = vl.y; al[i][2] = vl.z; al[i][3] = vl.w;
            }
            #pragma unroll
            for (int j = 0; j < 8; j++) {
                int word = (rowoff + j * 8) * BSTW + sub * 8 + tq;
                uint32_t bh0 = sB[word];
                uint32_t bh1 = sB[word + 4];
                uint32_t bl0 = sB[B_ARR_W + word];
                uint32_t bl1 = sB[B_ARR_W + word + 4];
                #pragma unroll
                for (int i = 0; i < 2; i++) {
                    MMA_BF16(acc[i][j], ah[i][0], ah[i][1], ah[i][2], ah[i][3], bh0, bh1);
                    MMA_BF16(acc[i][j], al[i][0], al[i][1], al[i][2], al[i][3], bh0, bh1);
                    MMA_BF16(acc[i][j], ah[i][0], ah[i][1], ah[i][2], ah[i][3], bl0, bl1);
                }
            }
        }

        if (tap == 8 && cc < 7) {
            __syncthreads();
            stageB(cc + 1);
            CP_COMMIT();
        }
    }

    // ---- epilogue: bias + LeakyReLU + store F + BN partials ----
    int timg = z >> 3, b = z & 7;
    int ncol = wid >> 2;
    float bias[2][2], psv[2][2] = {}, pqv[2][2] = {};
    #pragma unroll
    for (int i = 0; i < 2; i++)
        #pragma unroll
        for (int rh = 0; rh < 2; rh++)
            bias[i][rh] = b2[m0 + wm + i * 16 + g + rh * 8];

    #pragma unroll
    for (int i = 0; i < 2; i++) {
        #pragma unroll
        for (int j = 0; j < 8; j++) {
            #pragma unroll
            for (int r = 0; r < 4; r++) {
                int rh = r >> 1, c = r & 1;
                int m = wm + i * 16 + g + rh * 8;
                int np = nbase + wn + j * 8 + 2 * tq + c;
                int row = np / 34;
                int col = np - row * 34;
                if (row >= 1 && row <= 32 && col >= 1 && col <= 32) {
                    float v = acc[i][j][r] + bias[i][rh];
                    v = v > 0.f ? v : LRELU * v;
                    g_F[((size_t)z * 512 + m0 + m) * 1024 + (row - 1) * 32 + (col - 1)] = v;
                    psv[i][rh] += v;
                    pqv[i][rh] += v * v;
                }
            }
        }
    }
    #pragma unroll
    for (int i = 0; i < 2; i++) {
        #pragma unroll
        for (int rh = 0; rh < 2; rh++) {
            float s = psv[i][rh], q = pqv[i][rh];
            s += __shfl_xor_sync(0xffffffffu, s, 1);
            s += __shfl_xor_sync(0xffffffffu, s, 2);
            q += __shfl_xor_sync(0xffffffffu, q, 1);
            q += __shfl_xor_sync(0xffffffffu, q, 2);
            if (tq == 0) {
                int ch = timg * 512 + m0 + wm + i * 16 + g + rh * 8;
                int slot = (b * 9 + ntile) * 2 + ncol;
                g_psum [(size_t)ch * 144 + slot] = s;
                g_psumq[(size_t)ch * 144 + slot] = q;
            }
        }
    }
}

// ======================= BN stats (8 threads/channel, shuffle reduce) =======
__global__ void bn_stats_kernel(const float* __restrict__ gamma,
                                const float* __restrict__ bn_bias)
{
    int t = blockIdx.x * 256 + threadIdx.x;   // 8192 threads
    int i = t >> 3;                            // channel 0..1023
    int l8 = t & 7;
    float s = 0.f, q = 0.f;
    #pragma unroll
    for (int k = 0; k < 18; k++) {
        int p = l8 + k * 8;
        s += g_psum [(size_t)i * 144 + p];
        q += g_psumq[(size_t)i * 144 + p];
    }
    #pragma unroll
    for (int o = 4; o > 0; o >>= 1) {
        s += __shfl_xor_sync(0xffffffffu, s, o);
        q += __shfl_xor_sync(0xffffffffu, q, o);
    }
    if (l8 == 0) {
        const float inv_n = 1.0f / 8192.0f;
        float mean = s * inv_n;
        float var = q * inv_n - mean * mean;
        float a = gamma[i & 511] * rsqrtf(var + BN_EPS);
        g_bn_a[i] = a;
        g_bn_c[i] = bn_bias[i & 511] - mean * a;
    }
}

// ======================= scores GEMM (BN folded, bf16 3-term) =======
#define SMEM_SC ((4 * 128 * 36) * 4)
__global__ __launch_bounds__(256, 2) void scores_mma_kernel()
{
    extern __shared__ __align__(16) float smem[];
    float* sA = smem;
    float* sB = smem + 2 * 4608;
    uint32_t sA32 = smem_u32(sA), sB32 = smem_u32(sB);

    int tid = threadIdx.x, wid = tid >> 5, lane = tid & 31;
    int g = lane >> 2, tq = lane & 3;
    int n0 = blockIdx.x * 128, m0 = blockIdx.y * 128, b = blockIdx.z;
    const float* Ag = g_F + (size_t)b * 512 * 1024;
    const float* Bg = g_F + (size_t)(8 + b) * 512 * 1024;

    int wm = (wid & 3) * 32, wn = (wid >> 2) * 64;

    float asc[2][2], aof[2][2], bsc[8], bof[8];
    #pragma unroll
    for (int i = 0; i < 2; i++)
        #pragma unroll
        for (int rh = 0; rh < 2; rh++) {
            int ch = m0 + wm + i * 16 + g + rh * 8;
            asc[i][rh] = g_bn_a[ch];
            aof[i][rh] = g_bn_c[ch];
        }
    #pragma unroll
    for (int j = 0; j < 8; j++) {
        int ch = 512 + n0 + wn + j * 8 + g;
        bsc[j] = g_bn_a[ch];
        bof[j] = g_bn_c[ch];
    }

    float acc[2][8][4];
    #pragma unroll
    for (int i = 0; i < 2; i++)
        #pragma unroll
        for (int j = 0; j < 8; j++)
            #pragma unroll
            for (int r = 0; r < 4; r++) acc[i][j][r] = 0.f;

    auto stage = [&](int kc) {
        uint32_t baseA = sA32 + (uint32_t)((kc & 1) * 4608) * 4;
        uint32_t baseB = sB32 + (uint32_t)((kc & 1) * 4608) * 4;
        #pragma unroll
        for (int v = 0; v < 4; v++) {
            int task = tid + v * 256;
            int m = task >> 3, c4 = task & 7;
            CP16(baseA + (m * 36 + c4 * 4) * 4, Ag + (size_t)(m0 + m) * 1024 + kc * 32 + c4 * 4);
            CP16(baseB + (m * 36 + c4 * 4) * 4, Bg + (size_t)(n0 + m) * 1024 + kc * 32 + c4 * 4);
        }
    };

    stage(0); CP_COMMIT();

    for (int kc = 0; kc < 32; kc++) {
        CP_WAIT_ALL();
        __syncthreads();
        if (kc < 31) stage(kc + 1);
        CP_COMMIT();
        const float* sAp = sA + (kc & 1) * 4608;
        const float* sBp = sB + (kc & 1) * 4608;
        #pragma unroll
        for (int sub = 0; sub < 2; sub++) {
            uint32_t ah[2][4], al[2][4];
            #pragma unroll
            for (int i = 0; i < 2; i++) {
                const float* ap  = sAp + (wm + i * 16 + g) * 36 + sub * 16 + 2 * tq;
                const float* ap8 = ap + 8 * 36;
                float v00 = fmaf(ap[0],  asc[i][0], aof[i][0]);
                float v01 = fmaf(ap[1],  asc[i][0], aof[i][0]);
                float v02 = fmaf(ap[8],  asc[i][0], aof[i][0]);
                float v03 = fmaf(ap[9],  asc[i][0], aof[i][0]);
                float v10 = fmaf(ap8[0], asc[i][1], aof[i][1]);
                float v11 = fmaf(ap8[1], asc[i][1], aof[i][1]);
                float v12 = fmaf(ap8[8], asc[i][1], aof[i][1]);
                float v13 = fmaf(ap8[9], asc[i][1], aof[i][1]);
                splitbf(v00, v01, ah[i][0], al[i][0]);
                splitbf(v10, v11, ah[i][1], al[i][1]);
                splitbf(v02, v03, ah[i][2], al[i][2]);
                splitbf(v12, v13, ah[i][3], al[i][3]);
            }
            #pragma unroll
            for (int j = 0; j < 8; j++) {
                const float* bp = sBp + (wn + j * 8 + g) * 36 + sub * 16 + 2 * tq;
                float b0 = fmaf(bp[0], bsc[j], bof[j]);
                float b1 = fmaf(bp[1], bsc[j], bof[j]);
                float b2 = fmaf(bp[8], bsc[j], bof[j]);
                float b3 = fmaf(bp[9], bsc[j], bof[j]);
                uint32_t bh0, bl0, bh1, bl1;
                splitbf(b0, b1, bh0, bl0);
                splitbf(b2, b3, bh1, bl1);
                #pragma unroll
                for (int i = 0; i < 2; i++) {
                    MMA_BF16(acc[i][j], ah[i][0], ah[i][1], ah[i][2], ah[i][3], bh0, bh1);
                    MMA_BF16(acc[i][j], al[i][0], al[i][1], al[i][2], al[i][3], bh0, bh1);
                    MMA_BF16(acc[i][j], ah[i][0], ah[i][1], ah[i][2], ah[i][3], bl0, bl1);
                }
            }
        }
    }

    float* S = g_S + (size_t)b * 512 * 512;
    #pragma unroll
    for (int i = 0; i < 2; i++)
        #pragma unroll
        for (int j = 0; j < 8; j++)
            #pragma unroll
            for (int r = 0; r < 4; r++) {
                int m = m0 + wm + i * 16 + g + (r >> 1) * 8;
                int n = n0 + wn + j * 8 + 2 * tq + (r & 1);
                S[(size_t)m * 512 + n] = acc[i][j][r];
            }
}

// ======================= softmax =======================
__global__ void softmax_kernel()
{
    int row = blockIdx.x;
    float* s = g_S + (size_t)row * 512;
    int tid = threadIdx.x;

    float v0 = s[tid], v1 = s[tid + 256];
    float m = fmaxf(v0, v1);
    __shared__ float red[8];
    #pragma unroll
    for (int o = 16; o > 0; o >>= 1)
        m = fmaxf(m, __shfl_xor_sync(0xffffffffu, m, o));
    if ((tid & 31) == 0) red[tid >> 5] = m;
    __syncthreads();
    float M = fmaxf(fmaxf(fmaxf(red[0], red[1]), fmaxf(red[2], red[3])),
                    fmaxf(fmaxf(red[4], red[5]), fmaxf(red[6], red[7])));
    __syncthreads();

    float e0 = expf(v0 - M), e1 = expf(v1 - M);
    float sum = e0 + e1;
    #pragma unroll
    for (int o = 16; o > 0; o >>= 1)
        sum += __shfl_xor_sync(0xffffffffu, sum, o);
    if ((tid & 31) == 0) red[tid >> 5] = sum;
    __syncthreads();
    float T = red[0] + red[1] + red[2] + red[3] + red[4] + red[5] + red[6] + red[7];
    float inv = 1.0f / T;
    s[tid] = e0 * inv;
    s[tid + 256] = e1 * inv;
}

// ======================= out GEMM (bf16 3-term) ==========
#define SMEM_OUT ((2 * 128 * 36 + 2 * 32 * 140) * 4)
__global__ __launch_bounds__(256, 2) void out_mma_kernel(
    const float* __restrict__ x, const float* __restrict__ beta,
    float* __restrict__ out)
{
    extern __shared__ __align__(16) float smem[];
    float* sA = smem;
    float* sB = smem + 2 * 4608;
    uint32_t sA32 = smem_u32(sA), sB32 = smem_u32(sB);

    int tid = threadIdx.x, wid = tid >> 5, lane = tid & 31;
    int g = lane >> 2, tq = lane & 3;
    int n0 = blockIdx.x * 128, m0 = blockIdx.y * 128, b = blockIdx.z;
    const float* Ag = g_S + (size_t)b * 512 * 512;
    const float* X = x + (size_t)b * 512 * 1024;

    int wm = (wid & 3) * 32, wn = (wid >> 2) * 64;

    float acc[2][8][4];
    #pragma unroll
    for (int i = 0; i < 2; i++)
        #pragma unroll
        for (int j = 0; j < 8; j++)
            #pragma unroll
            for (int r = 0; r < 4; r++) acc[i][j][r] = 0.f;

    auto stageA = [&](int kc) {
        uint32_t base = sA32 + (uint32_t)((kc & 1) * 4608) * 4;
        #pragma unroll
        for (int v = 0; v < 4; v++) {
            int task = tid + v * 256;
            int m = task >> 3, c4 = task & 7;
            CP16(base + (m * 36 + c4 * 4) * 4, Ag + (size_t)(m0 + m) * 512 + kc * 32 + c4 * 4);
        }
    };
    auto stageB = [&](int kc) {
        uint32_t base = sB32 + (uint32_t)((kc & 1) * 4480) * 4;
        #pragma unroll
        for (int v = 0; v < 4; v++) {
            int task = tid + v * 256;
            int k = task >> 5, c4 = task & 31;
            CP16(base + (k * 140 + c4 * 4) * 4, X + (size_t)(kc * 32 + k) * 1024 + n0 + c4 * 4);
        }
    };

    stageA(0); stageB(0); CP_COMMIT();

    for (int kc = 0; kc < 16; kc++) {
        CP_WAIT_ALL();
        __syncthreads();
        if (kc < 15) { stageA(kc + 1); stageB(kc + 1); }
        CP_COMMIT();
        const float* sAp = sA + (kc & 1) * 4608;
        const float* sBp = sB + (kc & 1) * 4480;
        #pragma unroll
        for (int sub = 0; sub < 2; sub++) {
            uint32_t ah[2][4], al[2][4];
            #pragma unroll
            for (int i = 0; i < 2; i++) {
                const float* ap  = sAp + (wm + i * 16 + g) * 36 + sub * 16 + 2 * tq;
                const float* ap8 = ap + 8 * 36;
                splitbf(ap[0],  ap[1],  ah[i][0], al[i][0]);
                splitbf(ap8[0], ap8[1], ah[i][1], al[i][1]);
                splitbf(ap[8],  ap[9],  ah[i][2], al[i][2]);
                splitbf(ap8[8], ap8[9], ah[i][3], al[i][3]);
            }
            #pragma unroll
            for (int j = 0; j < 8; j++) {
                const float* bp = sBp + (sub * 16 + 2 * tq) * 140 + wn + j * 8 + g;
                uint32_t bh0, bl0, bh1, bl1;
                splitbf(bp[0],       bp[140],       bh0, bl0);
                splitbf(bp[8 * 140], bp[9 * 140],   bh1, bl1);
                #pragma unroll
                for (int i = 0; i < 2; i++) {
                    MMA_BF16(acc[i][j], ah[i][0], ah[i][1], ah[i][2], ah[i][3], bh0, bh1);
                    MMA_BF16(acc[i][j], al[i][0], al[i][1], al[i][2], al[i][3], bh0, bh1);
                    MMA_BF16(acc[i][j], ah[i][0], ah[i][1], ah[i][2], ah[i][3], bl0, bl1);
                }
            }
        }
    }

    float bt = beta[0];
    float* O = out + (size_t)b * 512 * 1024;
    #pragma unroll
    for (int i = 0; i < 2; i++)
        #pragma unroll
        for (int j = 0; j < 8; j++)
            #pragma unroll
            for (int r = 0; r < 4; r++) {
                int m = m0 + wm + i * 16 + g + (r >> 1) * 8;
                int n = n0 + wn + j * 8 + 2 * tq + (r & 1);
                O[(size_t)m * 1024 + n] = bt * acc[i][j][r];
            }
}

// ======================= launch =======================
extern "C" void kernel_launch(void* const* d_in, const int* in_sizes, int n_in,
                              void* d_out, int out_size)
{
    const float* x     = (const float*)d_in[0];
    const float* x1    = (const float*)d_in[1];
    const float* x2    = (const float*)d_in[2];
    const float* w1    = (const float*)d_in[3];
    const float* b1    = (const float*)d_in[4];
    const float* w2    = (const float*)d_in[5];
    const float* b2    = (const float*)d_in[6];
    const float* gamma = (const float*)d_in[7];
    const float* bnb   = (const float*)d_in[8];
    const float* beta  = (const float*)d_in[9];
    float* out = (float*)d_out;

    static int smem_set = 0;
    if (!smem_set) {
        cudaFuncSetAttribute(conv1x1t_kernel,     cudaFuncAttributeMaxDynamicSharedMemorySize, SMEM_C1);
        cudaFuncSetAttribute(conv3x3_bf16_kernel, cudaFuncAttributeMaxDynamicSharedMemorySize, SMEM_CONV);
        cudaFuncSetAttribute(scores_mma_kernel,   cudaFuncAttributeMaxDynamicSharedMemorySize, SMEM_SC);
        cudaFuncSetAttribute(out_mma_kernel,      cudaFuncAttributeMaxDynamicSharedMemorySize, SMEM_OUT);
        smem_set = 1;
    }

    w2pack_kernel<<<(9 * 8 * 4 * 2048 + 255) / 256, 256>>>(w2);

    conv1x1t_kernel<<<dim3(2, 8, 16), 256, SMEM_C1>>>(x1, x2, w1, b1);

    conv3x3_bf16_kernel<<<dim3(9, 4, 16), 256, SMEM_CONV>>>(b2);

    bn_stats_kernel<<<32, 256>>>(gamma, bnb);

    scores_mma_kernel<<<dim3(4, 4, 8), 256, SMEM_SC>>>();
    softmax_kernel<<<4096, 256>>>();

    out_mma_kernel<<<dim3(8, 4, 8), 256, SMEM_OUT>>>(x, beta, out);
}